// round 2
// baseline (speedup 1.0000x reference)
#include <cuda_runtime.h>
#include <math.h>

#define NUSER 50000
#define NPOST 100000
#define NENT  20000
#define EMAX  400000

// ---------------- scratch (static __device__, no allocation) ----------------
__device__ float g_f0_post[NPOST*64];
__device__ float g_f0_user[NUSER*64];
__device__ float g_f0_ent [NENT *64];
__device__ float g_f1_post[NPOST*64];
__device__ float g_f1_user[NUSER*64];
__device__ float g_f1_ent [NENT *64];
__device__ float g_hs [NPOST*128];
__device__ float g_als[NPOST*2];
__device__ float g_ald[NPOST*2];
__device__ unsigned int g_m[NPOST*2];
__device__ float g_s  [NPOST*2];
__device__ float g_e  [EMAX*2];
__device__ float g_u  [4*64];

// ---------------- helpers ----------------
__device__ __forceinline__ unsigned encf(float f) {
    unsigned u = __float_as_uint(f);
    return (u & 0x80000000u) ? ~u : (u | 0x80000000u);
}
__device__ __forceinline__ float decf(unsigned u) {
    return __uint_as_float((u & 0x80000000u) ? (u & 0x7FFFFFFFu) : ~u);
}
__device__ __forceinline__ void red_add_v2(float* addr, float a, float b) {
    asm volatile("red.global.add.v2.f32 [%0], {%1,%2};" :: "l"(addr), "f"(a), "f"(b) : "memory");
}

// ---------------- generic GEMM: Y[N,J] = X[N,K] @ W[J,K]^T (+bias) ----------
// blockDim.x = J/2, block handles 32 rows. K tiled by 64.
__global__ __launch_bounds__(64) void k_gemm(
    const float* __restrict__ X, const float* __restrict__ W,
    const float* __restrict__ bias, float* __restrict__ Y,
    int N, int K, int J)
{
    __shared__ float sW[64*132];   // sW[k*132 + j]
    __shared__ float sX[64*36];    // sX[k*36 + r]
    const int Jh = blockDim.x;     // J/2
    const int jx = threadIdx.x;
    const int row0 = blockIdx.x * 32;

    float acc0[32], acc1[32];
#pragma unroll
    for (int r = 0; r < 32; r++) { acc0[r] = 0.f; acc1[r] = 0.f; }

    const int ntiles = (K + 63) >> 6;
    for (int t = 0; t < ntiles; t++) {
        const int k0 = t << 6;
        for (int idx = jx; idx < 64 * J; idx += Jh) {
            int j = idx >> 6, k = idx & 63;
            sW[k*132 + j] = (k0 + k < K) ? W[j*K + k0 + k] : 0.f;
        }
        for (int idx = jx; idx < 64 * 32; idx += Jh) {
            int r = idx >> 6, k = idx & 63;
            int row = row0 + r;
            sX[k*36 + r] = (row < N && k0 + k < K) ? X[row*K + k0 + k] : 0.f;
        }
        __syncthreads();
#pragma unroll 4
        for (int k = 0; k < 64; k++) {
            float w0 = sW[k*132 + jx];
            float w1 = sW[k*132 + jx + Jh];
            const float4* xr = (const float4*)&sX[k*36];
#pragma unroll
            for (int r4 = 0; r4 < 8; r4++) {
                float4 xv = xr[r4];
                acc0[r4*4+0] += xv.x*w0; acc1[r4*4+0] += xv.x*w1;
                acc0[r4*4+1] += xv.y*w0; acc1[r4*4+1] += xv.y*w1;
                acc0[r4*4+2] += xv.z*w0; acc1[r4*4+2] += xv.z*w1;
                acc0[r4*4+3] += xv.w*w0; acc1[r4*4+3] += xv.w*w1;
            }
        }
        __syncthreads();
    }
    float b0 = bias ? bias[jx] : 0.f;
    float b1 = bias ? bias[jx + Jh] : 0.f;
    const int J2 = Jh * 2;
#pragma unroll 4
    for (int r = 0; r < 32; r++) {
        int row = row0 + r;
        if (row < N) {
            Y[row*J2 + jx]      = acc0[r] + b0;
            Y[row*J2 + jx + Jh] = acc1[r] + b1;
        }
    }
}

// ---------------- fold attention vectors: u[h,k] = sum_c a[h,c]*W[h*64+c,k] --
__global__ void k_prep_u(const float* __restrict__ a_s, const float* __restrict__ a_d,
                         const float* __restrict__ Ws, const float* __restrict__ Wd,
                         float* __restrict__ u)
{
    int t = threadIdx.x;          // 128 threads
    int h = t >> 6, k = t & 63;
    float us = 0.f, ud = 0.f;
#pragma unroll 8
    for (int c = 0; c < 64; c++) {
        us += a_s[h*64 + c] * Ws[(h*64 + c)*64 + k];
        ud += a_d[h*64 + c] * Wd[(h*64 + c)*64 + k];
    }
    u[t] = us; u[128 + t] = ud;
}

// ---------------- al[n,h] = x[n,:] . u[h,:] --------------------------------
__global__ void k_al(const float* __restrict__ x, const float* __restrict__ u,
                     float* __restrict__ al, int N)
{
    __shared__ float su[128];
    if (threadIdx.x < 128) su[threadIdx.x] = u[threadIdx.x];
    __syncthreads();
    int n = blockIdx.x * blockDim.x + threadIdx.x;
    if (n >= N) return;
    const float4* xr = (const float4*)(x + n*64);
    float d0 = 0.f, d1 = 0.f;
#pragma unroll
    for (int i = 0; i < 16; i++) {
        float4 v = xr[i];
        d0 += v.x*su[i*4] + v.y*su[i*4+1] + v.z*su[i*4+2] + v.w*su[i*4+3];
        d1 += v.x*su[64+i*4] + v.y*su[64+i*4+1] + v.z*su[64+i*4+2] + v.w*su[64+i*4+3];
    }
    al[n*2] = d0; al[n*2+1] = d1;
}

// ---------------- segment-state init ---------------------------------------
__global__ void k_init_seg(unsigned* __restrict__ m, float* __restrict__ s, int n) {
    int i = blockIdx.x * blockDim.x + threadIdx.x;
    if (i < n) { m[i] = 0x007FFFFFu; s[i] = 0.f; }   // enc(-inf)
}

// ---------------- dst-buffer init with summed relation biases ---------------
__global__ void k_init_bias3(float* __restrict__ buf, int N,
                             const float* b0, const float* b1, const float* b2)
{
    int i = blockIdx.x * blockDim.x + threadIdx.x;
    if (i >= N*64) return;
    int c = i & 63;
    float v = b0[c];
    if (b1) v += b1[c];
    if (b2) v += b2[c];
    buf[i] = v;
}

// ---------------- edge pass A: e = leaky(al_s[src]+al_d[dst]); seg max ------
__global__ void k_edge_a(const int* __restrict__ src, const int* __restrict__ dst, int E,
                         const float* __restrict__ als, const float* __restrict__ ald,
                         float* __restrict__ ebuf, unsigned* __restrict__ m)
{
    int e = blockIdx.x * blockDim.x + threadIdx.x;
    if (e >= E) return;
    int s = src[e], d = dst[e];
    float2 a = ((const float2*)als)[s];
    float2 b = ((const float2*)ald)[d];
    float e0 = a.x + b.x; e0 = e0 > 0.f ? e0 : 0.2f * e0;
    float e1 = a.y + b.y; e1 = e1 > 0.f ? e1 : 0.2f * e1;
    ((float2*)ebuf)[e] = make_float2(e0, e1);
    atomicMax(&m[d*2],     encf(e0));
    atomicMax(&m[d*2 + 1], encf(e1));
}

// ---------------- edge pass B: p = exp(e-m[dst]); seg sum -------------------
__global__ void k_edge_b(const int* __restrict__ dst, int E,
                         float* __restrict__ ebuf, const unsigned* __restrict__ m,
                         float* __restrict__ s)
{
    int e = blockIdx.x * blockDim.x + threadIdx.x;
    if (e >= E) return;
    int d = dst[e];
    float2 ev = ((const float2*)ebuf)[e];
    float p0 = expf(ev.x - decf(m[d*2]));
    float p1 = expf(ev.y - decf(m[d*2 + 1]));
    ((float2*)ebuf)[e] = make_float2(p0, p1);
    atomicAdd(&s[d*2],     p0);
    atomicAdd(&s[d*2 + 1], p1);
}

// ---------------- edge pass C: scatter 0.5*(a0*hs_h0 + a1*hs_h1) ------------
// one warp per edge, head-mean folded in -> 64 floats per edge via red.v2
__global__ void k_edge_c(const int* __restrict__ src, const int* __restrict__ dst, int E,
                         const float* __restrict__ pbuf, const float* __restrict__ sbuf,
                         const float* __restrict__ hs, float* __restrict__ nb)
{
    int gid = blockIdx.x * blockDim.x + threadIdx.x;
    int e = gid >> 5, lane = gid & 31;
    if (e >= E) return;
    int sN = src[e], dN = dst[e];
    float2 p  = ((const float2*)pbuf)[e];
    float2 ss = ((const float2*)sbuf)[dN];
    float a0 = p.x / (ss.x + 1e-16f);
    float a1 = p.y / (ss.y + 1e-16f);
    const float2* hr = (const float2*)hs + sN*64;
    float2 h0 = hr[lane];
    float2 h1 = hr[32 + lane];
    float vx = 0.5f * (a0*h0.x + a1*h1.x);
    float vy = 0.5f * (a0*h0.y + a1*h1.y);
    red_add_v2(nb + dN*64 + 2*lane, vx, vy);
}

// ---------------- relu in place ---------------------------------------------
__global__ void k_relu(float* __restrict__ x, int n) {
    int i = blockIdx.x * blockDim.x + threadIdx.x;
    if (i < n) x[i] = fmaxf(x[i], 0.f);
}

// ---------------- fused classifier ------------------------------------------
__global__ void k_cls(const float* __restrict__ hp,
                      const float* __restrict__ w1, const float* __restrict__ b1,
                      const float* __restrict__ w2, const float* __restrict__ b2,
                      float* __restrict__ out, int N)
{
    __shared__ float sw1[32*64];
    __shared__ float sb1[32];
    __shared__ float sw2[32];
    __shared__ float sb2;
    for (int i = threadIdx.x; i < 2048; i += blockDim.x) sw1[i] = w1[i];
    if (threadIdx.x < 32) { sb1[threadIdx.x] = b1[threadIdx.x]; sw2[threadIdx.x] = w2[threadIdx.x]; }
    if (threadIdx.x == 0) sb2 = b2[0];
    __syncthreads();
    int n = blockIdx.x * blockDim.x + threadIdx.x;
    if (n >= N) return;
    float xr[64];
    const float4* xp = (const float4*)(hp + n*64);
#pragma unroll
    for (int i = 0; i < 16; i++) {
        float4 v = xp[i];
        xr[i*4] = v.x; xr[i*4+1] = v.y; xr[i*4+2] = v.z; xr[i*4+3] = v.w;
    }
    float o = sb2;
#pragma unroll 4
    for (int j = 0; j < 32; j++) {
        float acc = sb1[j];
#pragma unroll
        for (int k = 0; k < 64; k++) acc += xr[k] * sw1[j*64 + k];
        o += fmaxf(acc, 0.f) * sw2[j];
    }
    out[n] = o;
}

// ---------------- host orchestration ----------------------------------------
struct RelCfg { int sidx, didx, xs_id, xd_id; };
// xs_id/xd_id: 0=user, 1=post, 2=ent
static const RelCfg g_rels[6] = {
    {3, 4,  0, 1},   // publish  user->post
    {5, 6,  0, 1},   // repost   user->post
    {7, 8,  1, 2},   // contain  post->ent
    {9, 10, 0, 0},   // interact user->user
    {11,12, 0, 0},   // follow   user->user
    {13,14, 1, 1},   // similar  post->post
};

extern "C" void kernel_launch(void* const* d_in, const int* in_sizes, int n_in,
                              void* d_out, int out_size)
{
    const float* x_post = (const float*)d_in[0];
    const float* x_user = (const float*)d_in[1];
    const float* x_ent  = (const float*)d_in[2];
    const float* post_w = (const float*)d_in[15];
    const float* post_b = (const float*)d_in[16];
    const float* user_w = (const float*)d_in[17];
    const float* user_b = (const float*)d_in[18];
    const float* ent_w  = (const float*)d_in[19];
    const float* ent_b  = (const float*)d_in[20];
    const float* W_src  = (const float*)d_in[21];
    const float* W_dst  = (const float*)d_in[22];
    const float* a_src  = (const float*)d_in[23];
    const float* a_dst  = (const float*)d_in[24];
    const float* gat_b  = (const float*)d_in[25];
    const float* cls_w1 = (const float*)d_in[26];
    const float* cls_b1 = (const float*)d_in[27];
    const float* cls_w2 = (const float*)d_in[28];
    const float* cls_b2 = (const float*)d_in[29];

    float *f0p, *f0u, *f0e, *f1p, *f1u, *f1e, *hs, *als, *ald, *sb, *eb, *ub;
    unsigned* mb;
    cudaGetSymbolAddress((void**)&f0p, g_f0_post);
    cudaGetSymbolAddress((void**)&f0u, g_f0_user);
    cudaGetSymbolAddress((void**)&f0e, g_f0_ent);
    cudaGetSymbolAddress((void**)&f1p, g_f1_post);
    cudaGetSymbolAddress((void**)&f1u, g_f1_user);
    cudaGetSymbolAddress((void**)&f1e, g_f1_ent);
    cudaGetSymbolAddress((void**)&hs,  g_hs);
    cudaGetSymbolAddress((void**)&als, g_als);
    cudaGetSymbolAddress((void**)&ald, g_ald);
    cudaGetSymbolAddress((void**)&mb,  g_m);
    cudaGetSymbolAddress((void**)&sb,  g_s);
    cudaGetSymbolAddress((void**)&eb,  g_e);
    cudaGetSymbolAddress((void**)&ub,  g_u);

    // initial projections
    k_gemm<<<(NPOST + 31)/32, 32>>>(x_post, post_w, post_b, f0p, NPOST, 768, 64);
    k_gemm<<<(NUSER + 31)/32, 32>>>(x_user, user_w, user_b, f0u, NUSER, 32, 64);
    k_gemm<<<(NENT  + 31)/32, 32>>>(x_ent,  ent_w,  ent_b,  f0e, NENT,  64, 64);

    float* cur[3] = { f0u, f0p, f0e };
    float* nxt[3] = { f1u, f1p, f1e };
    const int ncnt[3] = { NUSER, NPOST, NENT };

    for (int l = 0; l < 2; l++) {
        // init new buffers with summed biases of contributing relations
        k_init_bias3<<<(NPOST*64 + 255)/256, 256>>>(nxt[1], NPOST,
            gat_b + (l*6+0)*64, gat_b + (l*6+1)*64, gat_b + (l*6+5)*64);
        k_init_bias3<<<(NUSER*64 + 255)/256, 256>>>(nxt[0], NUSER,
            gat_b + (l*6+3)*64, gat_b + (l*6+4)*64, nullptr);
        k_init_bias3<<<(NENT*64 + 255)/256, 256>>>(nxt[2], NENT,
            gat_b + (l*6+2)*64, nullptr, nullptr);

        for (int r = 0; r < 6; r++) {
            const RelCfg& rc = g_rels[r];
            const int* srcp = (const int*)d_in[rc.sidx];
            const int* dstp = (const int*)d_in[rc.didx];
            int E  = in_sizes[rc.sidx];
            int Ns = ncnt[rc.xs_id];
            int Nd = ncnt[rc.xd_id];
            const float* xs = cur[rc.xs_id];
            const float* xd = cur[rc.xd_id];
            float* nb = nxt[rc.xd_id];
            int lr = l*6 + r;
            const float* Ws = W_src + lr*128*64;
            const float* Wd = W_dst + lr*128*64;
            const float* as = a_src + lr*128;
            const float* ad = a_dst + lr*128;

            k_prep_u<<<1, 128>>>(as, ad, Ws, Wd, ub);
            k_al<<<(Ns + 255)/256, 256>>>(xs, ub, als, Ns);
            k_al<<<(Nd + 255)/256, 256>>>(xd, ub + 128, ald, Nd);
            k_gemm<<<(Ns + 31)/32, 64>>>(xs, Ws, nullptr, hs, Ns, 64, 128);
            k_init_seg<<<(Nd*2 + 255)/256, 256>>>(mb, sb, Nd*2);
            k_edge_a<<<(E + 255)/256, 256>>>(srcp, dstp, E, als, ald, eb, mb);
            k_edge_b<<<(E + 255)/256, 256>>>(dstp, E, eb, mb, sb);
            long long tc = (long long)E * 32;
            k_edge_c<<<(int)((tc + 255)/256), 256>>>(srcp, dstp, E, eb, sb, hs, nb);
        }
        k_relu<<<(NPOST*64 + 255)/256, 256>>>(nxt[1], NPOST*64);
        k_relu<<<(NUSER*64 + 255)/256, 256>>>(nxt[0], NUSER*64);
        k_relu<<<(NENT*64  + 255)/256, 256>>>(nxt[2], NENT*64);
        for (int i = 0; i < 3; i++) { float* t = cur[i]; cur[i] = nxt[i]; nxt[i] = t; }
    }

    k_cls<<<(NPOST + 255)/256, 256>>>(cur[1], cls_w1, cls_b1, cls_w2, cls_b2,
                                      (float*)d_out, NPOST);
}

// round 3
// speedup vs baseline: 3.7880x; 3.7880x over previous
#include <cuda_runtime.h>
#include <math.h>

#define NUSER 50000
#define NPOST 100000
#define NENT  20000
#define SROWS 400000      // total hs/als rows over 6 relations
#define DROWS 420000      // total dst rows over 6 relations
#define ETOT  1550000

static inline int cdiv(int a, int b) { return (a + b - 1) / b; }

// ---------------- static scratch ----------------
__device__ float g_f0_post[NPOST*64];
__device__ float g_f0_user[NUSER*64];
__device__ float g_f0_ent [NENT *64];
__device__ float g_f1_post[NPOST*64];
__device__ float g_f1_user[NUSER*64];
__device__ float g_f1_ent [NENT *64];
__device__ float g_hs [SROWS*128];
__device__ float g_als[SROWS*2];
__device__ float g_ald[DROWS*2];
__device__ unsigned g_m[DROWS*2];
__device__ float g_s  [DROWS*2];
__device__ float g_e  [ETOT*2];
__device__ float g_u  [12*256];

// ---------------- helpers ----------------
__device__ __forceinline__ unsigned encf(float f) {
    unsigned u = __float_as_uint(f);
    return (u & 0x80000000u) ? ~u : (u | 0x80000000u);
}
__device__ __forceinline__ float decf(unsigned u) {
    return __uint_as_float((u & 0x80000000u) ? (u & 0x7FFFFFFFu) : ~u);
}
__device__ __forceinline__ void red_add_v4(float* a, float4 v) {
    asm volatile("red.global.add.v4.f32 [%0], {%1,%2,%3,%4};"
                 :: "l"(a), "f"(v.x), "f"(v.y), "f"(v.z), "f"(v.w) : "memory");
}

// ================= batched register-tiled GEMM =================
// Y[N,J] = X[N,K] @ W[J,K]^T (+bias, optional relu on X load)
// BM=128, BN=64, BK=16, 256 threads, 8x4 per-thread tile.
struct GemmSeg { const float* X; const float* W; const float* bias; float* Y;
                 int N; int K; int relu; };
struct GemmBatch { GemmSeg seg[6]; int off[7]; int nseg; int J; };

__global__ __launch_bounds__(256) void k_gemm_b(GemmBatch gb) {
    int b = blockIdx.x;
    int sg = 0;
    while (sg + 1 < gb.nseg && b >= gb.off[sg + 1]) sg++;
    const GemmSeg G = gb.seg[sg];
    const int row0 = (b - gb.off[sg]) * 128;
    const int j0 = blockIdx.y * 64;
    const int K = G.K, N = G.N, J = gb.J;

    __shared__ float sX[16][132];
    __shared__ float sW[16][68];

    const int tid = threadIdx.x;
    const int tm = tid >> 4, tn = tid & 15;

    float acc[8][4];
#pragma unroll
    for (int i = 0; i < 8; i++)
#pragma unroll
        for (int j = 0; j < 4; j++) acc[i][j] = 0.f;

    for (int k0 = 0; k0 < K; k0 += 16) {
#pragma unroll
        for (int q = 0; q < 2; q++) {
            int idx = tid + q * 256;
            int r = idx >> 2, kq = (idx & 3) << 2;
            float4 v = make_float4(0.f, 0.f, 0.f, 0.f);
            int row = row0 + r;
            if (row < N) v = *(const float4*)&G.X[row * K + k0 + kq];
            if (G.relu) {
                v.x = fmaxf(v.x, 0.f); v.y = fmaxf(v.y, 0.f);
                v.z = fmaxf(v.z, 0.f); v.w = fmaxf(v.w, 0.f);
            }
            sX[kq+0][r] = v.x; sX[kq+1][r] = v.y; sX[kq+2][r] = v.z; sX[kq+3][r] = v.w;
        }
        {
            int j = tid >> 2, kq = (tid & 3) << 2;
            float4 v = *(const float4*)&G.W[(j0 + j) * K + k0 + kq];
            sW[kq+0][j] = v.x; sW[kq+1][j] = v.y; sW[kq+2][j] = v.z; sW[kq+3][j] = v.w;
        }
        __syncthreads();
#pragma unroll
        for (int k = 0; k < 16; k++) {
            float4 x0 = *(const float4*)&sX[k][tm * 8];
            float4 x1 = *(const float4*)&sX[k][tm * 8 + 4];
            float4 w  = *(const float4*)&sW[k][tn * 4];
            float xv[8] = {x0.x, x0.y, x0.z, x0.w, x1.x, x1.y, x1.z, x1.w};
            float wv[4] = {w.x, w.y, w.z, w.w};
#pragma unroll
            for (int i = 0; i < 8; i++)
#pragma unroll
                for (int j = 0; j < 4; j++) acc[i][j] += xv[i] * wv[j];
        }
        __syncthreads();
    }

    float4 b4 = make_float4(0.f, 0.f, 0.f, 0.f);
    if (G.bias) b4 = *(const float4*)&G.bias[j0 + tn * 4];
#pragma unroll
    for (int i = 0; i < 8; i++) {
        int row = row0 + tm * 8 + i;
        if (row < N) {
            float4 o = make_float4(acc[i][0] + b4.x, acc[i][1] + b4.y,
                                   acc[i][2] + b4.z, acc[i][3] + b4.w);
            *(float4*)&G.Y[row * J + j0 + tn * 4] = o;
        }
    }
}

// ================= fold attention vectors (all 12 at once) =================
__global__ void k_prep_u_all(const float* __restrict__ a_s, const float* __restrict__ a_d,
                             const float* __restrict__ Ws, const float* __restrict__ Wd,
                             float* __restrict__ u) {
    int b = blockIdx.x;              // l*6+r
    int t = threadIdx.x;             // 128
    int h = t >> 6, k = t & 63;
    const float* as = a_s + b * 128;
    const float* ad = a_d + b * 128;
    const float* ws = Ws + b * 128 * 64;
    const float* wd = Wd + b * 128 * 64;
    float us = 0.f, ud = 0.f;
#pragma unroll 8
    for (int c = 0; c < 64; c++) {
        us += as[h*64 + c] * ws[(h*64 + c)*64 + k];
        ud += ad[h*64 + c] * wd[(h*64 + c)*64 + k];
    }
    u[b*256 + t] = us;
    u[b*256 + 128 + t] = ud;
}

// ================= batched al: per node type, multiple u-dots =================
struct AlJob { const float* u; float* out; };
struct AlSeg { const float* x; int N; int relu; int njobs; AlJob job[6]; };
struct AlBatch { AlSeg seg[3]; int off[4]; };

__global__ __launch_bounds__(256) void k_al_b(AlBatch ab) {
    int b = blockIdx.x;
    int sg = 0;
    while (sg + 1 < 3 && b >= ab.off[sg + 1]) sg++;
    const AlSeg S = ab.seg[sg];
    __shared__ float su[6*128];
    for (int i = threadIdx.x; i < S.njobs * 128; i += 256)
        su[i] = S.job[i >> 7].u[i & 127];
    __syncthreads();
    int n = (b - ab.off[sg]) * 256 + threadIdx.x;
    if (n >= S.N) return;
    float xr[64];
    const float4* xp = (const float4*)(S.x + n * 64);
#pragma unroll
    for (int i = 0; i < 16; i++) {
        float4 v = xp[i];
        if (S.relu) {
            v.x = fmaxf(v.x, 0.f); v.y = fmaxf(v.y, 0.f);
            v.z = fmaxf(v.z, 0.f); v.w = fmaxf(v.w, 0.f);
        }
        xr[i*4] = v.x; xr[i*4+1] = v.y; xr[i*4+2] = v.z; xr[i*4+3] = v.w;
    }
    for (int j = 0; j < S.njobs; j++) {
        const float* uu = su + j * 128;
        float d0 = 0.f, d1 = 0.f;
#pragma unroll
        for (int k = 0; k < 64; k++) { d0 += xr[k]*uu[k]; d1 += xr[k]*uu[64+k]; }
        S.job[j].out[n*2] = d0;
        S.job[j].out[n*2+1] = d1;
    }
}

// ================= per-layer init (bias-init nb + softmax state) =================
__global__ void k_init_layer(float* __restrict__ nbP, float* __restrict__ nbU,
                             float* __restrict__ nbE,
                             const float* bP0, const float* bP1, const float* bP2,
                             const float* bU0, const float* bU1, const float* bE0,
                             unsigned* __restrict__ m, float* __restrict__ s,
                             int oU, int oE, int oMS) {
    int b = blockIdx.x, t = threadIdx.x;
    if (b < oU) {
        int i = b * 256 + t; int c = i & 63;
        nbP[i] = bP0[c] + bP1[c] + bP2[c];
    } else if (b < oE) {
        int i = (b - oU) * 256 + t; int c = i & 63;
        nbU[i] = bU0[c] + bU1[c];
    } else if (b < oMS) {
        int i = (b - oE) * 256 + t; int c = i & 63;
        nbE[i] = bE0[c];
    } else {
        int i = (b - oMS) * 256 + t;
        if (i < DROWS * 2) { m[i] = 0x007FFFFFu; s[i] = 0.f; }
    }
}

// ================= batched edge passes =================
struct EdgeSeg {
    const int* src; const int* dst;
    float* e; const float* als; const float* ald;
    unsigned* m; float* s; const float* hs; float* nb;
    int E;
};
struct EdgeBatch { EdgeSeg seg[6]; int offA[7]; int offC[7]; };

__global__ __launch_bounds__(256) void k_edge_a_b(EdgeBatch eb) {
    int b = blockIdx.x;
    int sg = 0;
    while (sg + 1 < 6 && b >= eb.offA[sg + 1]) sg++;
    const EdgeSeg S = eb.seg[sg];
    int e = (b - eb.offA[sg]) * 256 + threadIdx.x;
    if (e >= S.E) return;
    int sN = S.src[e], dN = S.dst[e];
    float2 a  = ((const float2*)S.als)[sN];
    float2 bb = ((const float2*)S.ald)[dN];
    float e0 = a.x + bb.x; e0 = e0 > 0.f ? e0 : 0.2f * e0;
    float e1 = a.y + bb.y; e1 = e1 > 0.f ? e1 : 0.2f * e1;
    ((float2*)S.e)[e] = make_float2(e0, e1);
    atomicMax(&S.m[dN*2],     encf(e0));
    atomicMax(&S.m[dN*2 + 1], encf(e1));
}

__global__ __launch_bounds__(256) void k_edge_b_b(EdgeBatch eb) {
    int b = blockIdx.x;
    int sg = 0;
    while (sg + 1 < 6 && b >= eb.offA[sg + 1]) sg++;
    const EdgeSeg S = eb.seg[sg];
    int e = (b - eb.offA[sg]) * 256 + threadIdx.x;
    if (e >= S.E) return;
    int dN = S.dst[e];
    float2 ev = ((const float2*)S.e)[e];
    uint2 mm = ((const uint2*)S.m)[dN];
    float p0 = __expf(ev.x - decf(mm.x));
    float p1 = __expf(ev.y - decf(mm.y));
    ((float2*)S.e)[e] = make_float2(p0, p1);
    atomicAdd(&S.s[dN*2],     p0);
    atomicAdd(&S.s[dN*2 + 1], p1);
}

// 8 threads per edge; head-mean folded; red.v4 scatter
__global__ __launch_bounds__(256) void k_edge_c_b(EdgeBatch eb) {
    int b = blockIdx.x;
    int sg = 0;
    while (sg + 1 < 6 && b >= eb.offC[sg + 1]) sg++;
    const EdgeSeg S = eb.seg[sg];
    int t = (b - eb.offC[sg]) * 256 + threadIdx.x;
    int e = t >> 3, lane = t & 7;
    if (e >= S.E) return;
    int sN = S.src[e], dN = S.dst[e];
    float2 p  = ((const float2*)S.e)[e];
    float2 ss = ((const float2*)S.s)[dN];
    float a0 = 0.5f * p.x / (ss.x + 1e-16f);
    float a1 = 0.5f * p.y / (ss.y + 1e-16f);
    const float4* hr = (const float4*)(S.hs + sN * 128);
    float4 h0a = hr[lane*2],      h0b = hr[lane*2 + 1];
    float4 h1a = hr[16 + lane*2], h1b = hr[16 + lane*2 + 1];
    float4 v0 = make_float4(a0*h0a.x + a1*h1a.x, a0*h0a.y + a1*h1a.y,
                            a0*h0a.z + a1*h1a.z, a0*h0a.w + a1*h1a.w);
    float4 v1 = make_float4(a0*h0b.x + a1*h1b.x, a0*h0b.y + a1*h1b.y,
                            a0*h0b.z + a1*h1b.z, a0*h0b.w + a1*h1b.w);
    float* base = S.nb + dN * 64 + lane * 8;
    red_add_v4(base, v0);
    red_add_v4(base + 4, v1);
}

// ================= fused classifier (relu on load) =================
__global__ __launch_bounds__(256) void k_cls(const float* __restrict__ hp,
                      const float* __restrict__ w1, const float* __restrict__ b1,
                      const float* __restrict__ w2, const float* __restrict__ b2,
                      float* __restrict__ out, int N) {
    __shared__ float sw1[32*64];
    __shared__ float sb1[32];
    __shared__ float sw2[32];
    __shared__ float sb2;
    for (int i = threadIdx.x; i < 2048; i += blockDim.x) sw1[i] = w1[i];
    if (threadIdx.x < 32) { sb1[threadIdx.x] = b1[threadIdx.x]; sw2[threadIdx.x] = w2[threadIdx.x]; }
    if (threadIdx.x == 0) sb2 = b2[0];
    __syncthreads();
    int n = blockIdx.x * blockDim.x + threadIdx.x;
    if (n >= N) return;
    float xr[64];
    const float4* xp = (const float4*)(hp + n*64);
#pragma unroll
    for (int i = 0; i < 16; i++) {
        float4 v = xp[i];
        xr[i*4]   = fmaxf(v.x, 0.f); xr[i*4+1] = fmaxf(v.y, 0.f);
        xr[i*4+2] = fmaxf(v.z, 0.f); xr[i*4+3] = fmaxf(v.w, 0.f);
    }
    float o = sb2;
#pragma unroll 4
    for (int j = 0; j < 32; j++) {
        float acc = sb1[j];
#pragma unroll
        for (int k = 0; k < 64; k++) acc += xr[k] * sw1[j*64 + k];
        o += fmaxf(acc, 0.f) * sw2[j];
    }
    out[n] = o;
}

// ================= host orchestration =================
struct RelCfg { int sidx, didx, stype, dtype; };
// type: 0=user, 1=post, 2=ent
static const RelCfg g_rels[6] = {
    {3, 4,  0, 1},   // publish  user->post
    {5, 6,  0, 1},   // repost   user->post
    {7, 8,  1, 2},   // contain  post->ent
    {9, 10, 0, 0},   // interact user->user
    {11,12, 0, 0},   // follow   user->user
    {13,14, 1, 1},   // similar  post->post
};

extern "C" void kernel_launch(void* const* d_in, const int* in_sizes, int n_in,
                              void* d_out, int out_size)
{
    const float* x_post = (const float*)d_in[0];
    const float* x_user = (const float*)d_in[1];
    const float* x_ent  = (const float*)d_in[2];
    const float* post_w = (const float*)d_in[15];
    const float* post_b = (const float*)d_in[16];
    const float* user_w = (const float*)d_in[17];
    const float* user_b = (const float*)d_in[18];
    const float* ent_w  = (const float*)d_in[19];
    const float* ent_b  = (const float*)d_in[20];
    const float* W_src  = (const float*)d_in[21];
    const float* W_dst  = (const float*)d_in[22];
    const float* a_srcP = (const float*)d_in[23];
    const float* a_dstP = (const float*)d_in[24];
    const float* gat_b  = (const float*)d_in[25];
    const float* cls_w1 = (const float*)d_in[26];
    const float* cls_b1 = (const float*)d_in[27];
    const float* cls_w2 = (const float*)d_in[28];
    const float* cls_b2 = (const float*)d_in[29];

    float *f0p,*f0u,*f0e,*f1p,*f1u,*f1e,*hs,*als,*ald,*sb,*ebuf,*ub;
    unsigned* mb;
    cudaGetSymbolAddress((void**)&f0p, g_f0_post);
    cudaGetSymbolAddress((void**)&f0u, g_f0_user);
    cudaGetSymbolAddress((void**)&f0e, g_f0_ent);
    cudaGetSymbolAddress((void**)&f1p, g_f1_post);
    cudaGetSymbolAddress((void**)&f1u, g_f1_user);
    cudaGetSymbolAddress((void**)&f1e, g_f1_ent);
    cudaGetSymbolAddress((void**)&hs,  g_hs);
    cudaGetSymbolAddress((void**)&als, g_als);
    cudaGetSymbolAddress((void**)&ald, g_ald);
    cudaGetSymbolAddress((void**)&mb,  g_m);
    cudaGetSymbolAddress((void**)&sb,  g_s);
    cudaGetSymbolAddress((void**)&ebuf,g_e);
    cudaGetSymbolAddress((void**)&ub,  g_u);

    const int ncnt[3] = { NUSER, NPOST, NENT };

    // per-relation offsets
    int E[6], soff[6], doff[6], eoff[6];
    int sacc = 0, dacc = 0, eacc = 0;
    for (int r = 0; r < 6; r++) {
        E[r] = in_sizes[g_rels[r].sidx];
        soff[r] = sacc; sacc += ncnt[g_rels[r].stype];
        doff[r] = dacc; dacc += ncnt[g_rels[r].dtype];
        eoff[r] = eacc; eacc += E[r];
    }

    // 1. fold all attention vectors
    k_prep_u_all<<<12, 128>>>(a_srcP, a_dstP, W_src, W_dst, ub);

    // 2. batched input projections
    {
        GemmBatch pb;
        pb.J = 64; pb.nseg = 3;
        pb.seg[0] = { x_post, post_w, post_b, f0p, NPOST, 768, 0 };
        pb.seg[1] = { x_user, user_w, user_b, f0u, NUSER, 32, 0 };
        pb.seg[2] = { x_ent,  ent_w,  ent_b,  f0e, NENT,  64, 0 };
        pb.off[0] = 0;
        pb.off[1] = pb.off[0] + cdiv(NPOST, 128);
        pb.off[2] = pb.off[1] + cdiv(NUSER, 128);
        pb.off[3] = pb.off[2] + cdiv(NENT, 128);
        k_gemm_b<<<dim3(pb.off[3], 1), 256>>>(pb);
    }

    float* cur[3] = { f0u, f0p, f0e };
    float* nxt[3] = { f1u, f1p, f1e };

    for (int l = 0; l < 2; l++) {
        int relu = (l == 1);

        // init: nb biases + m/s
        {
            int oU  = (NPOST * 64) / 256;
            int oE  = oU + (NUSER * 64) / 256;
            int oMS = oE + (NENT * 64) / 256;
            int tot = oMS + cdiv(DROWS * 2, 256);
            k_init_layer<<<tot, 256>>>(nxt[1], nxt[0], nxt[2],
                gat_b + (l*6+0)*64, gat_b + (l*6+1)*64, gat_b + (l*6+5)*64,
                gat_b + (l*6+3)*64, gat_b + (l*6+4)*64, gat_b + (l*6+2)*64,
                mb, sb, oU, oE, oMS);
        }

        // batched hs GEMMs (all 6 relations)
        {
            GemmBatch hb;
            hb.J = 128; hb.nseg = 6;
            int acc = 0;
            for (int r = 0; r < 6; r++) {
                int Ns = ncnt[g_rels[r].stype];
                hb.seg[r] = { cur[g_rels[r].stype], W_src + (l*6+r)*128*64,
                              nullptr, hs + soff[r]*128, Ns, 64, relu };
                hb.off[r] = acc; acc += cdiv(Ns, 128);
            }
            hb.off[6] = acc;
            k_gemm_b<<<dim3(acc, 2), 256>>>(hb);
        }

        // batched al (user / post / ent segments)
        {
            AlBatch ab;
            // user: rel0 src, rel1 src, rel3 src+dst, rel4 src+dst
            ab.seg[0].x = cur[0]; ab.seg[0].N = NUSER; ab.seg[0].relu = relu; ab.seg[0].njobs = 6;
            ab.seg[0].job[0] = { ub + (l*6+0)*256,       als + soff[0]*2 };
            ab.seg[0].job[1] = { ub + (l*6+1)*256,       als + soff[1]*2 };
            ab.seg[0].job[2] = { ub + (l*6+3)*256,       als + soff[3]*2 };
            ab.seg[0].job[3] = { ub + (l*6+3)*256 + 128, ald + doff[3]*2 };
            ab.seg[0].job[4] = { ub + (l*6+4)*256,       als + soff[4]*2 };
            ab.seg[0].job[5] = { ub + (l*6+4)*256 + 128, ald + doff[4]*2 };
            // post: rel0 dst, rel1 dst, rel2 src, rel5 src+dst
            ab.seg[1].x = cur[1]; ab.seg[1].N = NPOST; ab.seg[1].relu = relu; ab.seg[1].njobs = 5;
            ab.seg[1].job[0] = { ub + (l*6+0)*256 + 128, ald + doff[0]*2 };
            ab.seg[1].job[1] = { ub + (l*6+1)*256 + 128, ald + doff[1]*2 };
            ab.seg[1].job[2] = { ub + (l*6+2)*256,       als + soff[2]*2 };
            ab.seg[1].job[3] = { ub + (l*6+5)*256,       als + soff[5]*2 };
            ab.seg[1].job[4] = { ub + (l*6+5)*256 + 128, ald + doff[5]*2 };
            ab.seg[1].job[5] = { nullptr, nullptr };
            // ent: rel2 dst
            ab.seg[2].x = cur[2]; ab.seg[2].N = NENT; ab.seg[2].relu = relu; ab.seg[2].njobs = 1;
            ab.seg[2].job[0] = { ub + (l*6+2)*256 + 128, ald + doff[2]*2 };
            for (int j = 1; j < 6; j++) ab.seg[2].job[j] = { nullptr, nullptr };
            ab.off[0] = 0;
            ab.off[1] = ab.off[0] + cdiv(NUSER, 256);
            ab.off[2] = ab.off[1] + cdiv(NPOST, 256);
            ab.off[3] = ab.off[2] + cdiv(NENT, 256);
            k_al_b<<<ab.off[3], 256>>>(ab);
        }

        // batched edge passes
        {
            EdgeBatch eb2;
            int accA = 0, accC = 0;
            for (int r = 0; r < 6; r++) {
                eb2.seg[r].src = (const int*)d_in[g_rels[r].sidx];
                eb2.seg[r].dst = (const int*)d_in[g_rels[r].didx];
                eb2.seg[r].e   = ebuf + eoff[r]*2;
                eb2.seg[r].als = als + soff[r]*2;
                eb2.seg[r].ald = ald + doff[r]*2;
                eb2.seg[r].m   = mb + doff[r]*2;
                eb2.seg[r].s   = sb + doff[r]*2;
                eb2.seg[r].hs  = hs + soff[r]*128;
                eb2.seg[r].nb  = nxt[g_rels[r].dtype];
                eb2.seg[r].E   = E[r];
                eb2.offA[r] = accA; accA += cdiv(E[r], 256);
                eb2.offC[r] = accC; accC += cdiv(E[r] * 8, 256);
            }
            eb2.offA[6] = accA; eb2.offC[6] = accC;
            k_edge_a_b<<<accA, 256>>>(eb2);
            k_edge_b_b<<<accA, 256>>>(eb2);
            k_edge_c_b<<<accC, 256>>>(eb2);
        }

        float* t;
        t = cur[0]; cur[0] = nxt[0]; nxt[0] = t;
        t = cur[1]; cur[1] = nxt[1]; nxt[1] = t;
        t = cur[2]; cur[2] = nxt[2]; nxt[2] = t;
    }

    k_cls<<<cdiv(NPOST, 256), 256>>>(cur[1], cls_w1, cls_b1, cls_w2, cls_b2,
                                     (float*)d_out, NPOST);
}

// round 6
// speedup vs baseline: 4.8931x; 1.2918x over previous
#include <cuda_runtime.h>
#include <cuda_bf16.h>
#include <cstdint>
#include <math.h>

#define NUSER 50000
#define NPOST 100000
#define NENT  20000
#define SROWS 400000      // total hs/als rows over 6 relations
#define DROWS 420000      // total dst rows over 6 relations
#define ETOT  1550000

static inline int cdiv(int a, int b) { return (a + b - 1) / b; }

// ---------------- static scratch ----------------
__device__ float g_f0_post[NPOST*64];
__device__ float g_f0_user[NUSER*64];
__device__ float g_f0_ent [NENT *64];
__device__ float g_f1_post[NPOST*64];
__device__ float g_f1_user[NUSER*64];
__device__ float g_f1_ent [NENT *64];
__device__ float g_hs [SROWS*128];
__device__ float g_als[SROWS*2];
__device__ float g_ald[DROWS*2];
__device__ unsigned g_m[DROWS*2];
__device__ float g_s  [DROWS*2];
__device__ float g_e  [ETOT*2];
__device__ float g_u  [12*256];

// ---------------- helpers ----------------
__device__ __forceinline__ unsigned encf(float f) {
    unsigned u = __float_as_uint(f);
    return (u & 0x80000000u) ? ~u : (u | 0x80000000u);
}
__device__ __forceinline__ float decf(unsigned u) {
    return __uint_as_float((u & 0x80000000u) ? (u & 0x7FFFFFFFu) : ~u);
}
__device__ __forceinline__ void red_add_v4(float* a, float4 v) {
    asm volatile("red.global.add.v4.f32 [%0], {%1,%2,%3,%4};"
                 :: "l"(a), "f"(v.x), "f"(v.y), "f"(v.z), "f"(v.w) : "memory");
}
__device__ __forceinline__ uint32_t smem_u32(const void* p) {
    return (uint32_t)__cvta_generic_to_shared(p);
}
__device__ __forceinline__ void ldsm_x4(uint32_t& r0, uint32_t& r1, uint32_t& r2,
                                        uint32_t& r3, uint32_t a) {
    asm volatile("ldmatrix.sync.aligned.m8n8.x4.shared.b16 {%0,%1,%2,%3}, [%4];"
                 : "=r"(r0), "=r"(r1), "=r"(r2), "=r"(r3) : "r"(a));
}
__device__ __forceinline__ void mma16816(float* c, const uint32_t* a, const uint32_t* b) {
    asm volatile("mma.sync.aligned.m16n8k16.row.col.f32.bf16.bf16.f32 "
                 "{%0,%1,%2,%3}, {%4,%5,%6,%7}, {%8,%9}, {%0,%1,%2,%3};"
                 : "+f"(c[0]), "+f"(c[1]), "+f"(c[2]), "+f"(c[3])
                 : "r"(a[0]), "r"(a[1]), "r"(a[2]), "r"(a[3]), "r"(b[0]), "r"(b[1]));
}
__device__ __forceinline__ void cvt_store(__nv_bfloat16* ph, __nv_bfloat16* pl, float4 v) {
    float f[4] = { v.x, v.y, v.z, v.w };
    __nv_bfloat162 h2[2], l2[2];
#pragma unroll
    for (int i = 0; i < 2; i++) {
        __nv_bfloat16 h0 = __float2bfloat16_rn(f[2*i]);
        __nv_bfloat16 h1 = __float2bfloat16_rn(f[2*i+1]);
        __nv_bfloat16 l0 = __float2bfloat16_rn(f[2*i]   - __bfloat162float(h0));
        __nv_bfloat16 l1 = __float2bfloat16_rn(f[2*i+1] - __bfloat162float(h1));
        h2[i] = __nv_bfloat162(h0, h1);
        l2[i] = __nv_bfloat162(l0, l1);
    }
    ((__nv_bfloat162*)ph)[0] = h2[0]; ((__nv_bfloat162*)ph)[1] = h2[1];
    ((__nv_bfloat162*)pl)[0] = l2[0]; ((__nv_bfloat162*)pl)[1] = l2[1];
}

// ================= batched tensor-core GEMM (bf16 split) =================
// Y[N,J] = X[N,K] @ W[J,K]^T (+bias, optional relu on X load)
// BM=128, BN=64 (per grid.y slice), BK=32, 256 threads, 8 warps (4m x 2n),
// warp tile 32x32, mma.m16n8k16 bf16 with 2-term split (3 MMAs per hi-pair).
#define XS 40   // smem row stride in bf16 elements (80B: conflict-free ldmatrix)

struct GemmSeg { const float* X; const float* W; const float* bias; float* Y;
                 int N; int K; int relu; };
struct GemmBatch { GemmSeg seg[6]; int off[7]; int nseg; int J; };

__global__ __launch_bounds__(256) void k_gemm_b(GemmBatch gb) {
    int b = blockIdx.x;
    int sg = 0;
    while (sg + 1 < gb.nseg && b >= gb.off[sg + 1]) sg++;
    const GemmSeg G = gb.seg[sg];
    const int row0 = (b - gb.off[sg]) * 128;
    const int j0 = blockIdx.y * 64;
    const int K = G.K, N = G.N, J = gb.J;

    __shared__ __align__(16) __nv_bfloat16 sXh[128*XS];
    __shared__ __align__(16) __nv_bfloat16 sXl[128*XS];
    __shared__ __align__(16) __nv_bfloat16 sWh[64*XS];
    __shared__ __align__(16) __nv_bfloat16 sWl[64*XS];

    const int tid = threadIdx.x;
    const int wid = tid >> 5, lane = tid & 31;
    const int m_base = (wid >> 1) * 32;   // 4 m-warps
    const int n_base = (wid & 1) * 32;    // 2 n-warps

    float acc[2][4][4];
#pragma unroll
    for (int i = 0; i < 2; i++)
#pragma unroll
        for (int j = 0; j < 4; j++)
#pragma unroll
            for (int q = 0; q < 4; q++) acc[i][j][q] = 0.f;

    const int lr = lane & 7, lq = lane >> 3;
    const int a_row = (lq & 1) * 8 + lr;   // within m16 tile
    const int a_kc  = (lq >> 1) * 8;
    const int b_row = (lq >> 1) * 8 + lr;  // within n16 group
    const int b_kc  = (lq & 1) * 8;

    for (int k0 = 0; k0 < K; k0 += 32) {
        // load + convert X tile [128 x 32]
#pragma unroll
        for (int q = 0; q < 4; q++) {
            int i = tid + q * 256;
            int r = i >> 3, c4 = (i & 7) * 4;
            int row = row0 + r;
            float4 v = make_float4(0.f, 0.f, 0.f, 0.f);
            if (row < N) v = *(const float4*)&G.X[(size_t)row * K + k0 + c4];
            if (G.relu) {
                v.x = fmaxf(v.x, 0.f); v.y = fmaxf(v.y, 0.f);
                v.z = fmaxf(v.z, 0.f); v.w = fmaxf(v.w, 0.f);
            }
            cvt_store(&sXh[r*XS + c4], &sXl[r*XS + c4], v);
        }
        // load + convert W tile [64 x 32]
#pragma unroll
        for (int q = 0; q < 2; q++) {
            int i = tid + q * 256;
            int r = i >> 3, c4 = (i & 7) * 4;
            float4 v = *(const float4*)&G.W[(size_t)(j0 + r) * K + k0 + c4];
            cvt_store(&sWh[r*XS + c4], &sWl[r*XS + c4], v);
        }
        __syncthreads();

#pragma unroll
        for (int kk = 0; kk < 32; kk += 16) {
            uint32_t Ah[2][4], Al[2][4], Bh[4][2], Bl[4][2];
#pragma unroll
            for (int im = 0; im < 2; im++) {
                int r = m_base + im * 16 + a_row;
                ldsm_x4(Ah[im][0], Ah[im][1], Ah[im][2], Ah[im][3],
                        smem_u32(&sXh[r*XS + kk + a_kc]));
                ldsm_x4(Al[im][0], Al[im][1], Al[im][2], Al[im][3],
                        smem_u32(&sXl[r*XS + kk + a_kc]));
            }
#pragma unroll
            for (int nn = 0; nn < 2; nn++) {
                int r = n_base + nn * 16 + b_row;
                uint32_t r0, r1, r2, r3;
                ldsm_x4(r0, r1, r2, r3, smem_u32(&sWh[r*XS + kk + b_kc]));
                Bh[nn*2][0] = r0; Bh[nn*2][1] = r1;
                Bh[nn*2+1][0] = r2; Bh[nn*2+1][1] = r3;
                ldsm_x4(r0, r1, r2, r3, smem_u32(&sWl[r*XS + kk + b_kc]));
                Bl[nn*2][0] = r0; Bl[nn*2][1] = r1;
                Bl[nn*2+1][0] = r2; Bl[nn*2+1][1] = r3;
            }
#pragma unroll
            for (int im = 0; im < 2; im++)
#pragma unroll
                for (int jn = 0; jn < 4; jn++) {
                    mma16816(acc[im][jn], Ah[im], Bh[jn]);
                    mma16816(acc[im][jn], Al[im], Bh[jn]);
                    mma16816(acc[im][jn], Ah[im], Bl[jn]);
                }
        }
        __syncthreads();
    }

    // epilogue
    const int r_lo = lane >> 2;
    const int c_lo = (lane & 3) * 2;
#pragma unroll
    for (int im = 0; im < 2; im++) {
#pragma unroll
        for (int jn = 0; jn < 4; jn++) {
            int col = j0 + n_base + jn * 8 + c_lo;
            float2 bb = make_float2(0.f, 0.f);
            if (G.bias) bb = *(const float2*)&G.bias[col];
            int row1 = row0 + m_base + im * 16 + r_lo;
            int row2 = row1 + 8;
            if (row1 < N)
                *(float2*)&G.Y[(size_t)row1 * J + col] =
                    make_float2(acc[im][jn][0] + bb.x, acc[im][jn][1] + bb.y);
            if (row2 < N)
                *(float2*)&G.Y[(size_t)row2 * J + col] =
                    make_float2(acc[im][jn][2] + bb.x, acc[im][jn][3] + bb.y);
        }
    }
}

// ================= fold attention vectors (all 12 at once) =================
__global__ void k_prep_u_all(const float* __restrict__ a_s, const float* __restrict__ a_d,
                             const float* __restrict__ Ws, const float* __restrict__ Wd,
                             float* __restrict__ u) {
    int b = blockIdx.x;              // l*6+r
    int t = threadIdx.x;             // 128
    int h = t >> 6, k = t & 63;
    const float* as = a_s + b * 128;
    const float* ad = a_d + b * 128;
    const float* ws = Ws + b * 128 * 64;
    const float* wd = Wd + b * 128 * 64;
    float us = 0.f, ud = 0.f;
#pragma unroll 8
    for (int c = 0; c < 64; c++) {
        us += as[h*64 + c] * ws[(h*64 + c)*64 + k];
        ud += ad[h*64 + c] * wd[(h*64 + c)*64 + k];
    }
    u[b*256 + t] = us;
    u[b*256 + 128 + t] = ud;
}

// ================= batched al: per node type, multiple u-dots =================
struct AlJob { const float* u; float* out; };
struct AlSeg { const float* x; int N; int relu; int njobs; AlJob job[6]; };
struct AlBatch { AlSeg seg[3]; int off[4]; };

__global__ __launch_bounds__(256) void k_al_b(AlBatch ab) {
    int b = blockIdx.x;
    int sg = 0;
    while (sg + 1 < 3 && b >= ab.off[sg + 1]) sg++;
    const AlSeg S = ab.seg[sg];
    __shared__ float su[6*128];
    for (int i = threadIdx.x; i < S.njobs * 128; i += 256)
        su[i] = S.job[i >> 7].u[i & 127];
    __syncthreads();
    int n = (b - ab.off[sg]) * 256 + threadIdx.x;
    if (n >= S.N) return;
    float xr[64];
    const float4* xp = (const float4*)(S.x + n * 64);
#pragma unroll
    for (int i = 0; i < 16; i++) {
        float4 v = xp[i];
        if (S.relu) {
            v.x = fmaxf(v.x, 0.f); v.y = fmaxf(v.y, 0.f);
            v.z = fmaxf(v.z, 0.f); v.w = fmaxf(v.w, 0.f);
        }
        xr[i*4] = v.x; xr[i*4+1] = v.y; xr[i*4+2] = v.z; xr[i*4+3] = v.w;
    }
    for (int j = 0; j < S.njobs; j++) {
        const float* uu = su + j * 128;
        float d0 = 0.f, d1 = 0.f;
#pragma unroll
        for (int k = 0; k < 64; k++) { d0 += xr[k]*uu[k]; d1 += xr[k]*uu[64+k]; }
        S.job[j].out[n*2] = d0;
        S.job[j].out[n*2+1] = d1;
    }
}

// ================= per-layer init (bias-init nb + softmax state) =================
__global__ void k_init_layer(float* __restrict__ nbP, float* __restrict__ nbU,
                             float* __restrict__ nbE,
                             const float* bP0, const float* bP1, const float* bP2,
                             const float* bU0, const float* bU1, const float* bE0,
                             unsigned* __restrict__ m, float* __restrict__ s,
                             int oU, int oE, int oMS) {
    int b = blockIdx.x, t = threadIdx.x;
    if (b < oU) {
        int i = b * 256 + t; int c = i & 63;
        nbP[i] = bP0[c] + bP1[c] + bP2[c];
    } else if (b < oE) {
        int i = (b - oU) * 256 + t; int c = i & 63;
        nbU[i] = bU0[c] + bU1[c];
    } else if (b < oMS) {
        int i = (b - oE) * 256 + t; int c = i & 63;
        nbE[i] = bE0[c];
    } else {
        int i = (b - oMS) * 256 + t;
        if (i < DROWS * 2) { m[i] = 0x007FFFFFu; s[i] = 0.f; }
    }
}

// ================= batched edge passes =================
struct EdgeSeg {
    const int* src; const int* dst;
    float* e; const float* als; const float* ald;
    unsigned* m; float* s; const float* hs; float* nb;
    int E;
};
struct EdgeBatch { EdgeSeg seg[6]; int offA[7]; int offC[7]; };

__global__ __launch_bounds__(256) void k_edge_a_b(EdgeBatch eb) {
    int b = blockIdx.x;
    int sg = 0;
    while (sg + 1 < 6 && b >= eb.offA[sg + 1]) sg++;
    const EdgeSeg S = eb.seg[sg];
    int e = (b - eb.offA[sg]) * 256 + threadIdx.x;
    if (e >= S.E) return;
    int sN = S.src[e], dN = S.dst[e];
    float2 a  = ((const float2*)S.als)[sN];
    float2 bb = ((const float2*)S.ald)[dN];
    float e0 = a.x + bb.x; e0 = e0 > 0.f ? e0 : 0.2f * e0;
    float e1 = a.y + bb.y; e1 = e1 > 0.f ? e1 : 0.2f * e1;
    ((float2*)S.e)[e] = make_float2(e0, e1);
    atomicMax(&S.m[dN*2],     encf(e0));
    atomicMax(&S.m[dN*2 + 1], encf(e1));
}

__global__ __launch_bounds__(256) void k_edge_b_b(EdgeBatch eb) {
    int b = blockIdx.x;
    int sg = 0;
    while (sg + 1 < 6 && b >= eb.offA[sg + 1]) sg++;
    const EdgeSeg S = eb.seg[sg];
    int e = (b - eb.offA[sg]) * 256 + threadIdx.x;
    if (e >= S.E) return;
    int dN = S.dst[e];
    float2 ev = ((const float2*)S.e)[e];
    uint2 mm = ((const uint2*)S.m)[dN];
    float p0 = __expf(ev.x - decf(mm.x));
    float p1 = __expf(ev.y - decf(mm.y));
    ((float2*)S.e)[e] = make_float2(p0, p1);
    atomicAdd(&S.s[dN*2],     p0);
    atomicAdd(&S.s[dN*2 + 1], p1);
}

// 8 threads per edge; head-mean folded; red.v4 scatter
__global__ __launch_bounds__(256) void k_edge_c_b(EdgeBatch eb) {
    int b = blockIdx.x;
    int sg = 0;
    while (sg + 1 < 6 && b >= eb.offC[sg + 1]) sg++;
    const EdgeSeg S = eb.seg[sg];
    int t = (b - eb.offC[sg]) * 256 + threadIdx.x;
    int e = t >> 3, lane = t & 7;
    if (e >= S.E) return;
    int sN = S.src[e], dN = S.dst[e];
    float2 p  = ((const float2*)S.e)[e];
    float2 ss = ((const float2*)S.s)[dN];
    float a0 = 0.5f * p.x / (ss.x + 1e-16f);
    float a1 = 0.5f * p.y / (ss.y + 1e-16f);
    const float4* hr = (const float4*)(S.hs + (size_t)sN * 128);
    float4 h0a = hr[lane*2],      h0b = hr[lane*2 + 1];
    float4 h1a = hr[16 + lane*2], h1b = hr[16 + lane*2 + 1];
    float4 v0 = make_float4(a0*h0a.x + a1*h1a.x, a0*h0a.y + a1*h1a.y,
                            a0*h0a.z + a1*h1a.z, a0*h0a.w + a1*h1a.w);
    float4 v1 = make_float4(a0*h0b.x + a1*h1b.x, a0*h0b.y + a1*h1b.y,
                            a0*h0b.z + a1*h1b.z, a0*h0b.w + a1*h1b.w);
    float* base = S.nb + (size_t)dN * 64 + lane * 8;
    red_add_v4(base, v0);
    red_add_v4(base + 4, v1);
}

// ================= fused classifier (relu on load) =================
__global__ __launch_bounds__(256) void k_cls(const float* __restrict__ hp,
                      const float* __restrict__ w1, const float* __restrict__ b1,
                      const float* __restrict__ w2, const float* __restrict__ b2,
                      float* __restrict__ out, int N) {
    __shared__ float sw1[32*64];
    __shared__ float sb1[32];
    __shared__ float sw2[32];
    __shared__ float sb2;
    for (int i = threadIdx.x; i < 2048; i += blockDim.x) sw1[i] = w1[i];
    if (threadIdx.x < 32) { sb1[threadIdx.x] = b1[threadIdx.x]; sw2[threadIdx.x] = w2[threadIdx.x]; }
    if (threadIdx.x == 0) sb2 = b2[0];
    __syncthreads();
    int n = blockIdx.x * blockDim.x + threadIdx.x;
    if (n >= N) return;
    float xr[64];
    const float4* xp = (const float4*)(hp + n*64);
#pragma unroll
    for (int i = 0; i < 16; i++) {
        float4 v = xp[i];
        xr[i*4]   = fmaxf(v.x, 0.f); xr[i*4+1] = fmaxf(v.y, 0.f);
        xr[i*4+2] = fmaxf(v.z, 0.f); xr[i*4+3] = fmaxf(v.w, 0.f);
    }
    float o = sb2;
#pragma unroll 4
    for (int j = 0; j < 32; j++) {
        float acc = sb1[j];
#pragma unroll
        for (int k = 0; k < 64; k++) acc += xr[k] * sw1[j*64 + k];
        o += fmaxf(acc, 0.f) * sw2[j];
    }
    out[n] = o;
}

// ================= host orchestration =================
struct RelCfg { int sidx, didx, stype, dtype; };
// type: 0=user, 1=post, 2=ent
static const RelCfg g_rels[6] = {
    {3, 4,  0, 1},   // publish  user->post
    {5, 6,  0, 1},   // repost   user->post
    {7, 8,  1, 2},   // contain  post->ent
    {9, 10, 0, 0},   // interact user->user
    {11,12, 0, 0},   // follow   user->user
    {13,14, 1, 1},   // similar  post->post
};

extern "C" void kernel_launch(void* const* d_in, const int* in_sizes, int n_in,
                              void* d_out, int out_size)
{
    const float* x_post = (const float*)d_in[0];
    const float* x_user = (const float*)d_in[1];
    const float* x_ent  = (const float*)d_in[2];
    const float* post_w = (const float*)d_in[15];
    const float* post_b = (const float*)d_in[16];
    const float* user_w = (const float*)d_in[17];
    const float* user_b = (const float*)d_in[18];
    const float* ent_w  = (const float*)d_in[19];
    const float* ent_b  = (const float*)d_in[20];
    const float* W_src  = (const float*)d_in[21];
    const float* W_dst  = (const float*)d_in[22];
    const float* a_srcP = (const float*)d_in[23];
    const float* a_dstP = (const float*)d_in[24];
    const float* gat_b  = (const float*)d_in[25];
    const float* cls_w1 = (const float*)d_in[26];
    const float* cls_b1 = (const float*)d_in[27];
    const float* cls_w2 = (const float*)d_in[28];
    const float* cls_b2 = (const float*)d_in[29];

    float *f0p,*f0u,*f0e,*f1p,*f1u,*f1e,*hs,*als,*ald,*sb,*ebuf,*ub;
    unsigned* mb;
    cudaGetSymbolAddress((void**)&f0p, g_f0_post);
    cudaGetSymbolAddress((void**)&f0u, g_f0_user);
    cudaGetSymbolAddress((void**)&f0e, g_f0_ent);
    cudaGetSymbolAddress((void**)&f1p, g_f1_post);
    cudaGetSymbolAddress((void**)&f1u, g_f1_user);
    cudaGetSymbolAddress((void**)&f1e, g_f1_ent);
    cudaGetSymbolAddress((void**)&hs,  g_hs);
    cudaGetSymbolAddress((void**)&als, g_als);
    cudaGetSymbolAddress((void**)&ald, g_ald);
    cudaGetSymbolAddress((void**)&mb,  g_m);
    cudaGetSymbolAddress((void**)&sb,  g_s);
    cudaGetSymbolAddress((void**)&ebuf,g_e);
    cudaGetSymbolAddress((void**)&ub,  g_u);

    const int ncnt[3] = { NUSER, NPOST, NENT };

    // per-relation offsets
    int E[6], soff[6], doff[6], eoff[6];
    int sacc = 0, dacc = 0, eacc = 0;
    for (int r = 0; r < 6; r++) {
        E[r] = in_sizes[g_rels[r].sidx];
        soff[r] = sacc; sacc += ncnt[g_rels[r].stype];
        doff[r] = dacc; dacc += ncnt[g_rels[r].dtype];
        eoff[r] = eacc; eacc += E[r];
    }

    // 1. fold all attention vectors
    k_prep_u_all<<<12, 128>>>(a_srcP, a_dstP, W_src, W_dst, ub);

    // 2. batched input projections
    {
        GemmBatch pb;
        pb.J = 64; pb.nseg = 3;
        pb.seg[0] = { x_post, post_w, post_b, f0p, NPOST, 768, 0 };
        pb.seg[1] = { x_user, user_w, user_b, f0u, NUSER, 32, 0 };
        pb.seg[2] = { x_ent,  ent_w,  ent_b,  f0e, NENT,  64, 0 };
        pb.off[0] = 0;
        pb.off[1] = pb.off[0] + cdiv(NPOST, 128);
        pb.off[2] = pb.off[1] + cdiv(NUSER, 128);
        pb.off[3] = pb.off[2] + cdiv(NENT, 128);
        k_gemm_b<<<dim3(pb.off[3], 1), 256>>>(pb);
    }

    float* cur[3] = { f0u, f0p, f0e };
    float* nxt[3] = { f1u, f1p, f1e };

    for (int l = 0; l < 2; l++) {
        int relu = (l == 1);

        // init: nb biases + m/s
        {
            int oU  = (NPOST * 64) / 256;
            int oE  = oU + (NUSER * 64) / 256;
            int oMS = oE + (NENT * 64) / 256;
            int tot = oMS + cdiv(DROWS * 2, 256);
            k_init_layer<<<tot, 256>>>(nxt[1], nxt[0], nxt[2],
                gat_b + (l*6+0)*64, gat_b + (l*6+1)*64, gat_b + (l*6+5)*64,
                gat_b + (l*6+3)*64, gat_b + (l*6+4)*64, gat_b + (l*6+2)*64,
                mb, sb, oU, oE, oMS);
        }

        // batched hs GEMMs (all 6 relations)
        {
            GemmBatch hb;
            hb.J = 128; hb.nseg = 6;
            int acc = 0;
            for (int r = 0; r < 6; r++) {
                int Ns = ncnt[g_rels[r].stype];
                hb.seg[r] = { cur[g_rels[r].stype], W_src + (size_t)(l*6+r)*128*64,
                              nullptr, hs + (size_t)soff[r]*128, Ns, 64, relu };
                hb.off[r] = acc; acc += cdiv(Ns, 128);
            }
            hb.off[6] = acc;
            k_gemm_b<<<dim3(acc, 2), 256>>>(hb);
        }

        // batched al (user / post / ent segments)
        {
            AlBatch ab;
            ab.seg[0].x = cur[0]; ab.seg[0].N = NUSER; ab.seg[0].relu = relu; ab.seg[0].njobs = 6;
            ab.seg[0].job[0] = { ub + (l*6+0)*256,       als + soff[0]*2 };
            ab.seg[0].job[1] = { ub + (l*6+1)*256,       als + soff[1]*2 };
            ab.seg[0].job[2] = { ub + (l*6+3)*256,       als + soff[3]*2 };
            ab.seg[0].job[3] = { ub + (l*6+3)*256 + 128, ald + doff[3]*2 };
            ab.seg[0].job[4] = { ub + (l*6+4)*256,       als + soff[4]*2 };
            ab.seg[0].job[5] = { ub + (l*6+4)*256 + 128, ald + doff[4]*2 };
            ab.seg[1].x = cur[1]; ab.seg[1].N = NPOST; ab.seg[1].relu = relu; ab.seg[1].njobs = 5;
            ab.seg[1].job[0] = { ub + (l*6+0)*256 + 128, ald + doff[0]*2 };
            ab.seg[1].job[1] = { ub + (l*6+1)*256 + 128, ald + doff[1]*2 };
            ab.seg[1].job[2] = { ub + (l*6+2)*256,       als + soff[2]*2 };
            ab.seg[1].job[3] = { ub + (l*6+5)*256,       als + soff[5]*2 };
            ab.seg[1].job[4] = { ub + (l*6+5)*256 + 128, ald + doff[5]*2 };
            ab.seg[1].job[5] = { nullptr, nullptr };
            ab.seg[2].x = cur[2]; ab.seg[2].N = NENT; ab.seg[2].relu = relu; ab.seg[2].njobs = 1;
            ab.seg[2].job[0] = { ub + (l*6+2)*256 + 128, ald + doff[2]*2 };
            for (int j = 1; j < 6; j++) ab.seg[2].job[j] = { nullptr, nullptr };
            ab.off[0] = 0;
            ab.off[1] = ab.off[0] + cdiv(NUSER, 256);
            ab.off[2] = ab.off[1] + cdiv(NPOST, 256);
            ab.off[3] = ab.off[2] + cdiv(NENT, 256);
            k_al_b<<<ab.off[3], 256>>>(ab);
        }

        // batched edge passes
        {
            EdgeBatch eb2;
            int accA = 0, accC = 0;
            for (int r = 0; r < 6; r++) {
                eb2.seg[r].src = (const int*)d_in[g_rels[r].sidx];
                eb2.seg[r].dst = (const int*)d_in[g_rels[r].didx];
                eb2.seg[r].e   = ebuf + (size_t)eoff[r]*2;
                eb2.seg[r].als = als + soff[r]*2;
                eb2.seg[r].ald = ald + doff[r]*2;
                eb2.seg[r].m   = mb + doff[r]*2;
                eb2.seg[r].s   = sb + doff[r]*2;
                eb2.seg[r].hs  = hs + (size_t)soff[r]*128;
                eb2.seg[r].nb  = nxt[g_rels[r].dtype];
                eb2.seg[r].E   = E[r];
                eb2.offA[r] = accA; accA += cdiv(E[r], 256);
                eb2.offC[r] = accC; accC += cdiv(E[r] * 8, 256);
            }
            eb2.offA[6] = accA; eb2.offC[6] = accC;
            k_edge_a_b<<<accA, 256>>>(eb2);
            k_edge_b_b<<<accA, 256>>>(eb2);
            k_edge_c_b<<<accC, 256>>>(eb2);
        }

        float* t;
        t = cur[0]; cur[0] = nxt[0]; nxt[0] = t;
        t = cur[1]; cur[1] = nxt[1]; nxt[1] = t;
        t = cur[2]; cur[2] = nxt[2]; nxt[2] = t;
    }

    k_cls<<<cdiv(NPOST, 256), 256>>>(cur[1], cls_w1, cls_b1, cls_w2, cls_b2,
                                     (float*)d_out, NPOST);
}

// round 9
// speedup vs baseline: 4.9218x; 1.0059x over previous
#include <cuda_runtime.h>
#include <cuda_bf16.h>
#include <cuda_fp16.h>
#include <cstdint>
#include <math.h>

#define NUSER 50000
#define NPOST 100000
#define NENT  20000
#define NNODE 170000      // user + post + ent
#define SROWS 400000      // total hs rows over 6 relations
#define DROWS 420000      // total dst rows over 6 relations
#define ETOT  1550000

static inline int cdiv(int a, int b) { return (a + b - 1) / b; }

// ---------------- static scratch ----------------
__device__ float g_f0_post[NPOST*64];
__device__ float g_f0_user[NUSER*64];
__device__ float g_f0_ent [NENT *64];
__device__ float g_f1_post[NPOST*64];
__device__ float g_f1_user[NUSER*64];
__device__ float g_f1_ent [NENT *64];
__device__ __nv_bfloat16 g_xh[(size_t)NNODE*64];
__device__ __nv_bfloat16 g_xl[(size_t)NNODE*64];
__device__ __half g_hs[(size_t)SROWS*128];
__device__ float g_als[SROWS*2];
__device__ float g_ald[DROWS*2];
__device__ unsigned g_m[DROWS*2];
__device__ float g_s  [DROWS*2];
__device__ float g_e  [ETOT*2];
__device__ float g_u  [12*256];

// ---------------- helpers ----------------
__device__ __forceinline__ unsigned encf(float f) {
    unsigned u = __float_as_uint(f);
    return (u & 0x80000000u) ? ~u : (u | 0x80000000u);
}
__device__ __forceinline__ float decf(unsigned u) {
    return __uint_as_float((u & 0x80000000u) ? (u & 0x7FFFFFFFu) : ~u);
}
__device__ __forceinline__ void red_add_v4(float* a, float4 v) {
    asm volatile("red.global.add.v4.f32 [%0], {%1,%2,%3,%4};"
                 :: "l"(a), "f"(v.x), "f"(v.y), "f"(v.z), "f"(v.w) : "memory");
}
__device__ __forceinline__ uint32_t smem_u32(const void* p) {
    return (uint32_t)__cvta_generic_to_shared(p);
}
__device__ __forceinline__ void ldsm_x4(uint32_t& r0, uint32_t& r1, uint32_t& r2,
                                        uint32_t& r3, uint32_t a) {
    asm volatile("ldmatrix.sync.aligned.m8n8.x4.shared.b16 {%0,%1,%2,%3}, [%4];"
                 : "=r"(r0), "=r"(r1), "=r"(r2), "=r"(r3) : "r"(a));
}
__device__ __forceinline__ void mma16816(float* c, const uint32_t* a, const uint32_t* b) {
    asm volatile("mma.sync.aligned.m16n8k16.row.col.f32.bf16.bf16.f32 "
                 "{%0,%1,%2,%3}, {%4,%5,%6,%7}, {%8,%9}, {%0,%1,%2,%3};"
                 : "+f"(c[0]), "+f"(c[1]), "+f"(c[2]), "+f"(c[3])
                 : "r"(a[0]), "r"(a[1]), "r"(a[2]), "r"(a[3]), "r"(b[0]), "r"(b[1]));
}
__device__ __forceinline__ void cvt_store(__nv_bfloat16* ph, __nv_bfloat16* pl, float4 v) {
    float f[4] = { v.x, v.y, v.z, v.w };
    __nv_bfloat162 h2[2], l2[2];
#pragma unroll
    for (int i = 0; i < 2; i++) {
        __nv_bfloat16 h0 = __float2bfloat16_rn(f[2*i]);
        __nv_bfloat16 h1 = __float2bfloat16_rn(f[2*i+1]);
        __nv_bfloat16 l0 = __float2bfloat16_rn(f[2*i]   - __bfloat162float(h0));
        __nv_bfloat16 l1 = __float2bfloat16_rn(f[2*i+1] - __bfloat162float(h1));
        h2[i] = __nv_bfloat162(h0, h1);
        l2[i] = __nv_bfloat162(l0, l1);
    }
    ((__nv_bfloat162*)ph)[0] = h2[0]; ((__nv_bfloat162*)ph)[1] = h2[1];
    ((__nv_bfloat162*)pl)[0] = l2[0]; ((__nv_bfloat162*)pl)[1] = l2[1];
}

// ================= batched tensor-core GEMM (bf16 split) =================
// PAIR=0: X fp32 (+relu), Y fp32 (+bias)  — input projections
// PAIR=1: X pre-split bf16 hi/lo, Y fp16  — hs GEMMs
#define XS 40   // smem row stride in bf16 elements (80B: conflict-free ldmatrix)

struct GemmSeg { const float* X; const __nv_bfloat16* Xh; const __nv_bfloat16* Xl;
                 const float* W; const float* bias; float* Y; __half* Yh;
                 int N; int K; int relu; };
struct GemmBatch { GemmSeg seg[6]; int off[7]; int nseg; int J; };

template<int PAIR>
__global__ __launch_bounds__(256) void k_gemm_t(GemmBatch gb) {
    int b = blockIdx.x;
    int sg = 0;
    while (sg + 1 < gb.nseg && b >= gb.off[sg + 1]) sg++;
    const GemmSeg G = gb.seg[sg];
    const int row0 = (b - gb.off[sg]) * 128;
    const int j0 = blockIdx.y * 64;
    const int K = G.K, N = G.N, J = gb.J;

    __shared__ __align__(16) __nv_bfloat16 sXh[128*XS];
    __shared__ __align__(16) __nv_bfloat16 sXl[128*XS];
    __shared__ __align__(16) __nv_bfloat16 sWh[64*XS];
    __shared__ __align__(16) __nv_bfloat16 sWl[64*XS];

    const int tid = threadIdx.x;
    const int wid = tid >> 5, lane = tid & 31;
    const int m_base = (wid >> 1) * 32;   // 4 m-warps
    const int n_base = (wid & 1) * 32;    // 2 n-warps

    float acc[2][4][4];
#pragma unroll
    for (int i = 0; i < 2; i++)
#pragma unroll
        for (int j = 0; j < 4; j++)
#pragma unroll
            for (int q = 0; q < 4; q++) acc[i][j][q] = 0.f;

    const int lr = lane & 7, lq = lane >> 3;
    const int a_row = (lq & 1) * 8 + lr;
    const int a_kc  = (lq >> 1) * 8;
    const int b_row = (lq >> 1) * 8 + lr;
    const int b_kc  = (lq & 1) * 8;

    for (int k0 = 0; k0 < K; k0 += 32) {
        if (PAIR) {
            // X tile [128 x 32] bf16 hi/lo, direct 16B copies
#pragma unroll
            for (int q = 0; q < 2; q++) {
                int i = tid + q * 256;
                int r = i >> 2, c8 = (i & 3) * 8;
                int row = row0 + r;
                uint4 vh = make_uint4(0,0,0,0), vl = make_uint4(0,0,0,0);
                if (row < N) {
                    vh = *(const uint4*)&G.Xh[(size_t)row * 64 + k0 + c8];
                    vl = *(const uint4*)&G.Xl[(size_t)row * 64 + k0 + c8];
                }
                *(uint4*)&sXh[r*XS + c8] = vh;
                *(uint4*)&sXl[r*XS + c8] = vl;
            }
        } else {
#pragma unroll
            for (int q = 0; q < 4; q++) {
                int i = tid + q * 256;
                int r = i >> 3, c4 = (i & 7) * 4;
                int row = row0 + r;
                float4 v = make_float4(0.f, 0.f, 0.f, 0.f);
                if (row < N) v = *(const float4*)&G.X[(size_t)row * K + k0 + c4];
                if (G.relu) {
                    v.x = fmaxf(v.x, 0.f); v.y = fmaxf(v.y, 0.f);
                    v.z = fmaxf(v.z, 0.f); v.w = fmaxf(v.w, 0.f);
                }
                cvt_store(&sXh[r*XS + c4], &sXl[r*XS + c4], v);
            }
        }
        // W tile [64 x 32] from fp32
#pragma unroll
        for (int q = 0; q < 2; q++) {
            int i = tid + q * 256;
            int r = i >> 3, c4 = (i & 7) * 4;
            float4 v = *(const float4*)&G.W[(size_t)(j0 + r) * K + k0 + c4];
            cvt_store(&sWh[r*XS + c4], &sWl[r*XS + c4], v);
        }
        __syncthreads();

#pragma unroll
        for (int kk = 0; kk < 32; kk += 16) {
            uint32_t Ah[2][4], Al[2][4], Bh[4][2], Bl[4][2];
#pragma unroll
            for (int im = 0; im < 2; im++) {
                int r = m_base + im * 16 + a_row;
                ldsm_x4(Ah[im][0], Ah[im][1], Ah[im][2], Ah[im][3],
                        smem_u32(&sXh[r*XS + kk + a_kc]));
                ldsm_x4(Al[im][0], Al[im][1], Al[im][2], Al[im][3],
                        smem_u32(&sXl[r*XS + kk + a_kc]));
            }
#pragma unroll
            for (int nn = 0; nn < 2; nn++) {
                int r = n_base + nn * 16 + b_row;
                uint32_t r0, r1, r2, r3;
                ldsm_x4(r0, r1, r2, r3, smem_u32(&sWh[r*XS + kk + b_kc]));
                Bh[nn*2][0] = r0; Bh[nn*2][1] = r1;
                Bh[nn*2+1][0] = r2; Bh[nn*2+1][1] = r3;
                ldsm_x4(r0, r1, r2, r3, smem_u32(&sWl[r*XS + kk + b_kc]));
                Bl[nn*2][0] = r0; Bl[nn*2][1] = r1;
                Bl[nn*2+1][0] = r2; Bl[nn*2+1][1] = r3;
            }
#pragma unroll
            for (int im = 0; im < 2; im++)
#pragma unroll
                for (int jn = 0; jn < 4; jn++) {
                    mma16816(acc[im][jn], Ah[im], Bh[jn]);
                    mma16816(acc[im][jn], Al[im], Bh[jn]);
                    mma16816(acc[im][jn], Ah[im], Bl[jn]);
                }
        }
        __syncthreads();
    }

    // epilogue
    const int r_lo = lane >> 2;
    const int c_lo = (lane & 3) * 2;
#pragma unroll
    for (int im = 0; im < 2; im++) {
#pragma unroll
        for (int jn = 0; jn < 4; jn++) {
            int col = j0 + n_base + jn * 8 + c_lo;
            int row1 = row0 + m_base + im * 16 + r_lo;
            int row2 = row1 + 8;
            if (PAIR) {
                if (row1 < N)
                    *(__half2*)&G.Yh[(size_t)row1 * J + col] =
                        __floats2half2_rn(acc[im][jn][0], acc[im][jn][1]);
                if (row2 < N)
                    *(__half2*)&G.Yh[(size_t)row2 * J + col] =
                        __floats2half2_rn(acc[im][jn][2], acc[im][jn][3]);
            } else {
                float2 bb = make_float2(0.f, 0.f);
                if (G.bias) bb = *(const float2*)&G.bias[col];
                if (row1 < N)
                    *(float2*)&G.Y[(size_t)row1 * J + col] =
                        make_float2(acc[im][jn][0] + bb.x, acc[im][jn][1] + bb.y);
                if (row2 < N)
                    *(float2*)&G.Y[(size_t)row2 * J + col] =
                        make_float2(acc[im][jn][2] + bb.x, acc[im][jn][3] + bb.y);
            }
        }
    }
}

// ================= fold attention vectors (all 12 at once) =================
__global__ void k_prep_u_all(const float* __restrict__ a_s, const float* __restrict__ a_d,
                             const float* __restrict__ Ws, const float* __restrict__ Wd,
                             float* __restrict__ u) {
    int b = blockIdx.x;              // l*6+r
    int t = threadIdx.x;             // 128
    int h = t >> 6, k = t & 63;
    const float* as = a_s + b * 128;
    const float* ad = a_d + b * 128;
    const float* ws = Ws + b * 128 * 64;
    const float* wd = Wd + b * 128 * 64;
    float us = 0.f, ud = 0.f;
#pragma unroll 8
    for (int c = 0; c < 64; c++) {
        us += as[h*64 + c] * ws[(h*64 + c)*64 + k];
        ud += ad[h*64 + c] * wd[(h*64 + c)*64 + k];
    }
    u[b*256 + t] = us;
    u[b*256 + 128 + t] = ud;
}

// ================= cvt (f32 -> bf16 hi/lo, relu) + all al dots ==============
struct AlJob { const float* u; float* out; };
struct AlSeg { const float* x; __nv_bfloat16* xh; __nv_bfloat16* xl;
               int N; int relu; int njobs; AlJob job[6]; };
struct AlBatch { AlSeg seg[3]; int off[4]; };

__global__ __launch_bounds__(256) void k_cvt_al_b(AlBatch ab) {
    int b = blockIdx.x;
    int sg = 0;
    while (sg + 1 < 3 && b >= ab.off[sg + 1]) sg++;
    const AlSeg S = ab.seg[sg];
    __shared__ float su[6*128];
    for (int i = threadIdx.x; i < S.njobs * 128; i += 256)
        su[i] = S.job[i >> 7].u[i & 127];
    __syncthreads();
    int n = (b - ab.off[sg]) * 256 + threadIdx.x;
    if (n >= S.N) return;
    float xr[64];
    const float4* xp = (const float4*)(S.x + (size_t)n * 64);
#pragma unroll
    for (int i = 0; i < 16; i++) {
        float4 v = xp[i];
        if (S.relu) {
            v.x = fmaxf(v.x, 0.f); v.y = fmaxf(v.y, 0.f);
            v.z = fmaxf(v.z, 0.f); v.w = fmaxf(v.w, 0.f);
        }
        xr[i*4] = v.x; xr[i*4+1] = v.y; xr[i*4+2] = v.z; xr[i*4+3] = v.w;
    }
    // write bf16 hi/lo pair (16B chunks)
#pragma unroll
    for (int i = 0; i < 8; i++) {
        uint32_t hw[4], lw[4];
#pragma unroll
        for (int j = 0; j < 4; j++) {
            float f0 = xr[i*8 + 2*j], f1 = xr[i*8 + 2*j + 1];
            __nv_bfloat16 h0 = __float2bfloat16_rn(f0);
            __nv_bfloat16 h1 = __float2bfloat16_rn(f1);
            __nv_bfloat16 l0 = __float2bfloat16_rn(f0 - __bfloat162float(h0));
            __nv_bfloat16 l1 = __float2bfloat16_rn(f1 - __bfloat162float(h1));
            __nv_bfloat162 hp(h0, h1), lp(l0, l1);
            hw[j] = *(uint32_t*)&hp; lw[j] = *(uint32_t*)&lp;
        }
        *(uint4*)&S.xh[(size_t)n*64 + i*8] = make_uint4(hw[0], hw[1], hw[2], hw[3]);
        *(uint4*)&S.xl[(size_t)n*64 + i*8] = make_uint4(lw[0], lw[1], lw[2], lw[3]);
    }
    for (int j = 0; j < S.njobs; j++) {
        const float* uu = su + j * 128;
        float d0 = 0.f, d1 = 0.f;
#pragma unroll
        for (int k = 0; k < 64; k++) { d0 += xr[k]*uu[k]; d1 += xr[k]*uu[64+k]; }
        S.job[j].out[n*2] = d0;
        S.job[j].out[n*2+1] = d1;
    }
}

// ================= per-layer init (bias-init nb + softmax state) =================
__global__ void k_init_layer(float* __restrict__ nbP, float* __restrict__ nbU,
                             float* __restrict__ nbE,
                             const float* bP0, const float* bP1, const float* bP2,
                             const float* bU0, const float* bU1, const float* bE0,
                             unsigned* __restrict__ m, float* __restrict__ s,
                             int oU, int oE, int oMS) {
    int b = blockIdx.x, t = threadIdx.x;
    if (b < oU) {
        int i = b * 256 + t; int c = i & 63;
        nbP[i] = bP0[c] + bP1[c] + bP2[c];
    } else if (b < oE) {
        int i = (b - oU) * 256 + t; int c = i & 63;
        nbU[i] = bU0[c] + bU1[c];
    } else if (b < oMS) {
        int i = (b - oE) * 256 + t; int c = i & 63;
        nbE[i] = bE0[c];
    } else {
        int i = (b - oMS) * 256 + t;
        if (i < DROWS * 2) { m[i] = 0x007FFFFFu; s[i] = 0.f; }
    }
}

// ================= batched edge passes =================
struct EdgeSeg {
    const int* src; const int* dst;
    float* e; const float* als; const float* ald;
    unsigned* m; float* s; const __half* hs; float* nb;
    int E;
};
struct EdgeBatch { EdgeSeg seg[6]; int offA[7]; int offC[7]; };

__global__ __launch_bounds__(256) void k_edge_a_b(EdgeBatch eb) {
    int b = blockIdx.x;
    int sg = 0;
    while (sg + 1 < 6 && b >= eb.offA[sg + 1]) sg++;
    const EdgeSeg S = eb.seg[sg];
    int e = (b - eb.offA[sg]) * 256 + threadIdx.x;
    if (e >= S.E) return;
    int sN = S.src[e], dN = S.dst[e];
    float2 a  = ((const float2*)S.als)[sN];
    float2 bb = ((const float2*)S.ald)[dN];
    float e0 = a.x + bb.x; e0 = e0 > 0.f ? e0 : 0.2f * e0;
    float e1 = a.y + bb.y; e1 = e1 > 0.f ? e1 : 0.2f * e1;
    ((float2*)S.e)[e] = make_float2(e0, e1);
    atomicMax(&S.m[dN*2],     encf(e0));
    atomicMax(&S.m[dN*2 + 1], encf(e1));
}

__global__ __launch_bounds__(256) void k_edge_b_b(EdgeBatch eb) {
    int b = blockIdx.x;
    int sg = 0;
    while (sg + 1 < 6 && b >= eb.offA[sg + 1]) sg++;
    const EdgeSeg S = eb.seg[sg];
    int e = (b - eb.offA[sg]) * 256 + threadIdx.x;
    if (e >= S.E) return;
    int dN = S.dst[e];
    float2 ev = ((const float2*)S.e)[e];
    uint2 mm = ((const uint2*)S.m)[dN];
    float p0 = __expf(ev.x - decf(mm.x));
    float p1 = __expf(ev.y - decf(mm.y));
    ((float2*)S.e)[e] = make_float2(p0, p1);
    atomicAdd(&S.s[dN*2],     p0);
    atomicAdd(&S.s[dN*2 + 1], p1);
}

// 8 threads per edge; head-mean folded; hs in fp16; red.v4 scatter
__global__ __launch_bounds__(256) void k_edge_c_b(EdgeBatch eb) {
    int b = blockIdx.x;
    int sg = 0;
    while (sg + 1 < 6 && b >= eb.offC[sg + 1]) sg++;
    const EdgeSeg S = eb.seg[sg];
    int t = (b - eb.offC[sg]) * 256 + threadIdx.x;
    int e = t >> 3, lane = t & 7;
    if (e >= S.E) return;
    int sN = S.src[e], dN = S.dst[e];
    float2 p  = ((const float2*)S.e)[e];
    float2 ss = ((const float2*)S.s)[dN];
    float a0 = 0.5f * p.x / (ss.x + 1e-16f);
    float a1 = 0.5f * p.y / (ss.y + 1e-16f);
    const __half* hr = S.hs + (size_t)sN * 128;
    int c0 = lane * 8;
    uint4 u0 = *(const uint4*)&hr[c0];        // head0 cols c0..c0+7
    uint4 u1 = *(const uint4*)&hr[64 + c0];   // head1 cols c0..c0+7
    const __half2* h0 = (const __half2*)&u0;
    const __half2* h1 = (const __half2*)&u1;
    float o[8];
#pragma unroll
    for (int j = 0; j < 4; j++) {
        float2 f0 = __half22float2(h0[j]);
        float2 f1 = __half22float2(h1[j]);
        o[2*j]   = a0*f0.x + a1*f1.x;
        o[2*j+1] = a0*f0.y + a1*f1.y;
    }
    float* base = S.nb + (size_t)dN * 64 + c0;
    red_add_v4(base,     make_float4(o[0], o[1], o[2], o[3]));
    red_add_v4(base + 4, make_float4(o[4], o[5], o[6], o[7]));
}

// ================= fused classifier (relu on load) =================
__global__ __launch_bounds__(256) void k_cls(const float* __restrict__ hp,
                      const float* __restrict__ w1, const float* __restrict__ b1,
                      const float* __restrict__ w2, const float* __restrict__ b2,
                      float* __restrict__ out, int N) {
    __shared__ float sw1[32*64];
    __shared__ float sb1[32];
    __shared__ float sw2[32];
    __shared__ float sb2;
    for (int i = threadIdx.x; i < 2048; i += blockDim.x) sw1[i] = w1[i];
    if (threadIdx.x < 32) { sb1[threadIdx.x] = b1[threadIdx.x]; sw2[threadIdx.x] = w2[threadIdx.x]; }
    if (threadIdx.x == 0) sb2 = b2[0];
    __syncthreads();
    int n = blockIdx.x * blockDim.x + threadIdx.x;
    if (n >= N) return;
    float xr[64];
    const float4* xp = (const float4*)(hp + (size_t)n*64);
#pragma unroll
    for (int i = 0; i < 16; i++) {
        float4 v = xp[i];
        xr[i*4]   = fmaxf(v.x, 0.f); xr[i*4+1] = fmaxf(v.y, 0.f);
        xr[i*4+2] = fmaxf(v.z, 0.f); xr[i*4+3] = fmaxf(v.w, 0.f);
    }
    float o = sb2;
#pragma unroll 4
    for (int j = 0; j < 32; j++) {
        float acc = sb1[j];
#pragma unroll
        for (int k = 0; k < 64; k++) acc += xr[k] * sw1[j*64 + k];
        o += fmaxf(acc, 0.f) * sw2[j];
    }
    out[n] = o;
}

// ================= host orchestration =================
struct RelCfg { int sidx, didx, stype, dtype; };
// type: 0=user, 1=post, 2=ent
static const RelCfg g_rels[6] = {
    {3, 4,  0, 1},   // publish  user->post
    {5, 6,  0, 1},   // repost   user->post
    {7, 8,  1, 2},   // contain  post->ent
    {9, 10, 0, 0},   // interact user->user
    {11,12, 0, 0},   // follow   user->user
    {13,14, 1, 1},   // similar  post->post
};

extern "C" void kernel_launch(void* const* d_in, const int* in_sizes, int n_in,
                              void* d_out, int out_size)
{
    const float* x_post = (const float*)d_in[0];
    const float* x_user = (const float*)d_in[1];
    const float* x_ent  = (const float*)d_in[2];
    const float* post_w = (const float*)d_in[15];
    const float* post_b = (const float*)d_in[16];
    const float* user_w = (const float*)d_in[17];
    const float* user_b = (const float*)d_in[18];
    const float* ent_w  = (const float*)d_in[19];
    const float* ent_b  = (const float*)d_in[20];
    const float* W_src  = (const float*)d_in[21];
    const float* W_dst  = (const float*)d_in[22];
    const float* a_srcP = (const float*)d_in[23];
    const float* a_dstP = (const float*)d_in[24];
    const float* gat_b  = (const float*)d_in[25];
    const float* cls_w1 = (const float*)d_in[26];
    const float* cls_b1 = (const float*)d_in[27];
    const float* cls_w2 = (const float*)d_in[28];
    const float* cls_b2 = (const float*)d_in[29];

    float *f0p,*f0u,*f0e,*f1p,*f1u,*f1e,*als,*ald,*sb,*ebuf,*ub;
    __nv_bfloat16 *xh, *xl;
    __half* hsb;
    unsigned* mb;
    cudaGetSymbolAddress((void**)&f0p, g_f0_post);
    cudaGetSymbolAddress((void**)&f0u, g_f0_user);
    cudaGetSymbolAddress((void**)&f0e, g_f0_ent);
    cudaGetSymbolAddress((void**)&f1p, g_f1_post);
    cudaGetSymbolAddress((void**)&f1u, g_f1_user);
    cudaGetSymbolAddress((void**)&f1e, g_f1_ent);
    cudaGetSymbolAddress((void**)&xh,  g_xh);
    cudaGetSymbolAddress((void**)&xl,  g_xl);
    cudaGetSymbolAddress((void**)&hsb, g_hs);
    cudaGetSymbolAddress((void**)&als, g_als);
    cudaGetSymbolAddress((void**)&ald, g_ald);
    cudaGetSymbolAddress((void**)&mb,  g_m);
    cudaGetSymbolAddress((void**)&sb,  g_s);
    cudaGetSymbolAddress((void**)&ebuf,g_e);
    cudaGetSymbolAddress((void**)&ub,  g_u);

    const int ncnt[3] = { NUSER, NPOST, NENT };
    const int toff[3] = { 0, NUSER, NUSER + NPOST };   // node-pair buffer offsets

    // per-relation offsets
    int E[6], soff[6], doff[6], eoff[6];
    int sacc = 0, dacc = 0, eacc = 0;
    for (int r = 0; r < 6; r++) {
        E[r] = in_sizes[g_rels[r].sidx];
        soff[r] = sacc; sacc += ncnt[g_rels[r].stype];
        doff[r] = dacc; dacc += ncnt[g_rels[r].dtype];
        eoff[r] = eacc; eacc += E[r];
    }

    // 1. fold all attention vectors
    k_prep_u_all<<<12, 128>>>(a_srcP, a_dstP, W_src, W_dst, ub);

    // 2. batched input projections (fp32 path)
    {
        GemmBatch pb;
        pb.J = 64; pb.nseg = 3;
        pb.seg[0] = { x_post, nullptr, nullptr, post_w, post_b, f0p, nullptr, NPOST, 768, 0 };
        pb.seg[1] = { x_user, nullptr, nullptr, user_w, user_b, f0u, nullptr, NUSER, 32, 0 };
        pb.seg[2] = { x_ent,  nullptr, nullptr, ent_w,  ent_b,  f0e, nullptr, NENT,  64, 0 };
        pb.off[0] = 0;
        pb.off[1] = pb.off[0] + cdiv(NPOST, 128);
        pb.off[2] = pb.off[1] + cdiv(NUSER, 128);
        pb.off[3] = pb.off[2] + cdiv(NENT, 128);
        k_gemm_t<0><<<dim3(pb.off[3], 1), 256>>>(pb);
    }

    float* cur[3] = { f0u, f0p, f0e };
    float* nxt[3] = { f1u, f1p, f1e };

    for (int l = 0; l < 2; l++) {
        int relu = (l == 1);

        // init: nb biases + m/s
        {
            int oU  = (NPOST * 64) / 256;
            int oE  = oU + (NUSER * 64) / 256;
            int oMS = oE + (NENT * 64) / 256;
            int tot = oMS + cdiv(DROWS * 2, 256);
            k_init_layer<<<tot, 256>>>(nxt[1], nxt[0], nxt[2],
                gat_b + (l*6+0)*64, gat_b + (l*6+1)*64, gat_b + (l*6+5)*64,
                gat_b + (l*6+3)*64, gat_b + (l*6+4)*64, gat_b + (l*6+2)*64,
                mb, sb, oU, oE, oMS);
        }

        // cvt to bf16 pair + all al dots
        {
            AlBatch ab;
            ab.seg[0].x = cur[0]; ab.seg[0].xh = xh + (size_t)toff[0]*64;
            ab.seg[0].xl = xl + (size_t)toff[0]*64;
            ab.seg[0].N = NUSER; ab.seg[0].relu = relu; ab.seg[0].njobs = 6;
            ab.seg[0].job[0] = { ub + (l*6+0)*256,       als + soff[0]*2 };
            ab.seg[0].job[1] = { ub + (l*6+1)*256,       als + soff[1]*2 };
            ab.seg[0].job[2] = { ub + (l*6+3)*256,       als + soff[3]*2 };
            ab.seg[0].job[3] = { ub + (l*6+3)*256 + 128, ald + doff[3]*2 };
            ab.seg[0].job[4] = { ub + (l*6+4)*256,       als + soff[4]*2 };
            ab.seg[0].job[5] = { ub + (l*6+4)*256 + 128, ald + doff[4]*2 };
            ab.seg[1].x = cur[1]; ab.seg[1].xh = xh + (size_t)toff[1]*64;
            ab.seg[1].xl = xl + (size_t)toff[1]*64;
            ab.seg[1].N = NPOST; ab.seg[1].relu = relu; ab.seg[1].njobs = 5;
            ab.seg[1].job[0] = { ub + (l*6+0)*256 + 128, ald + doff[0]*2 };
            ab.seg[1].job[1] = { ub + (l*6+1)*256 + 128, ald + doff[1]*2 };
            ab.seg[1].job[2] = { ub + (l*6+2)*256,       als + soff[2]*2 };
            ab.seg[1].job[3] = { ub + (l*6+5)*256,       als + soff[5]*2 };
            ab.seg[1].job[4] = { ub + (l*6+5)*256 + 128, ald + doff[5]*2 };
            ab.seg[1].job[5] = { nullptr, nullptr };
            ab.seg[2].x = cur[2]; ab.seg[2].xh = xh + (size_t)toff[2]*64;
            ab.seg[2].xl = xl + (size_t)toff[2]*64;
            ab.seg[2].N = NENT; ab.seg[2].relu = relu; ab.seg[2].njobs = 1;
            ab.seg[2].job[0] = { ub + (l*6+2)*256 + 128, ald + doff[2]*2 };
            for (int j = 1; j < 6; j++) ab.seg[2].job[j] = { nullptr, nullptr };
            ab.off[0] = 0;
            ab.off[1] = ab.off[0] + cdiv(NUSER, 256);
            ab.off[2] = ab.off[1] + cdiv(NPOST, 256);
            ab.off[3] = ab.off[2] + cdiv(NENT, 256);
            k_cvt_al_b<<<ab.off[3], 256>>>(ab);
        }

        // batched hs GEMMs (pair path, fp16 out)
        {
            GemmBatch hb;
            hb.J = 128; hb.nseg = 6;
            int acc = 0;
            for (int r = 0; r < 6; r++) {
                int st = g_rels[r].stype;
                int Ns = ncnt[st];
                hb.seg[r] = { nullptr, xh + (size_t)toff[st]*64, xl + (size_t)toff[st]*64,
                              W_src + (size_t)(l*6+r)*128*64, nullptr, nullptr,
                              hsb + (size_t)soff[r]*128, Ns, 64, 0 };
                hb.off[r] = acc; acc += cdiv(Ns, 128);
            }
            hb.off[6] = acc;
            k_gemm_t<1><<<dim3(acc, 2), 256>>>(hb);
        }

        // batched edge passes
        {
            EdgeBatch eb2;
            int accA = 0, accC = 0;
            for (int r = 0; r < 6; r++) {
                eb2.seg[r].src = (const int*)d_in[g_rels[r].sidx];
                eb2.seg[r].dst = (const int*)d_in[g_rels[r].didx];
                eb2.seg[r].e   = ebuf + (size_t)eoff[r]*2;
                eb2.seg[r].als = als + soff[r]*2;
                eb2.seg[r].ald = ald + doff[r]*2;
                eb2.seg[r].m   = mb + doff[r]*2;
                eb2.seg[r].s   = sb + doff[r]*2;
                eb2.seg[r].hs  = hsb + (size_t)soff[r]*128;
                eb2.seg[r].nb  = nxt[g_rels[r].dtype];
                eb2.seg[r].E   = E[r];
                eb2.offA[r] = accA; accA += cdiv(E[r], 256);
                eb2.offC[r] = accC; accC += cdiv(E[r] * 8, 256);
            }
            eb2.offA[6] = accA; eb2.offC[6] = accC;
            k_edge_a_b<<<accA, 256>>>(eb2);
            k_edge_b_b<<<accA, 256>>>(eb2);
            k_edge_c_b<<<accC, 256>>>(eb2);
        }

        float* t;
        t = cur[0]; cur[0] = nxt[0]; nxt[0] = t;
        t = cur[1]; cur[1] = nxt[1]; nxt[1] = t;
        t = cur[2]; cur[2] = nxt[2]; nxt[2] = t;
    }

    k_cls<<<cdiv(NPOST, 256), 256>>>(cur[1], cls_w1, cls_b1, cls_w2, cls_b2,
                                     (float*)d_out, NPOST);
}